// round 7
// baseline (speedup 1.0000x reference)
#include <cuda_runtime.h>
#include <cuda_bf16.h>
#include <math.h>
#include <cstdint>

// ---------------- problem constants ----------------
#define H_DIM    3584
#define NH       28
#define NKV      4
#define HD       128
#define GROUP    7
#define BATCH    4
#define SEQ      1024
#define TTOK     4096
#define QKV_OUT  4608
#define NBLK     512
#define BSZ      16
#define CACHE_HALF (NBLK*BSZ*NKV*HD)
#define SCALE    0.08838834764831845f
#define RLN10K   0.1439115671349322f

#define KDIM     3584
#define BK       16
#define NCHUNK   224           // KDIM / BK

// ---------------- scratch ----------------
__device__ float g_qkv[(size_t)TTOK * QKV_OUT];
__device__ __nv_bfloat16 g_h_hi[(size_t)TTOK * KDIM];
__device__ __nv_bfloat16 g_h_lo[(size_t)TTOK * KDIM];
__device__ __nv_bfloat16 g_wq_hi[(size_t)QKV_OUT * KDIM];
__device__ __nv_bfloat16 g_wq_lo[(size_t)QKV_OUT * KDIM];
__device__ __nv_bfloat16 g_wo_hi[(size_t)H_DIM * KDIM];
__device__ __nv_bfloat16 g_wo_lo[(size_t)H_DIM * KDIM];
__device__ __nv_bfloat16 g_c_hi[(size_t)TTOK * KDIM];
__device__ __nv_bfloat16 g_c_lo[(size_t)TTOK * KDIM];
// attention operands (bf16 hi/lo)
__device__ __nv_bfloat16 g_q_hi[(size_t)TTOK * NH * HD];
__device__ __nv_bfloat16 g_q_lo[(size_t)TTOK * NH * HD];
__device__ __nv_bfloat16 g_k_hi[(size_t)BATCH * NKV * SEQ * HD];
__device__ __nv_bfloat16 g_k_lo[(size_t)BATCH * NKV * SEQ * HD];
__device__ __nv_bfloat16 g_v_hi[(size_t)BATCH * NKV * SEQ * HD];
__device__ __nv_bfloat16 g_v_lo[(size_t)BATCH * NKV * SEQ * HD];

// ---------------- helpers ----------------
__device__ __forceinline__ uint32_t smem_u32(const void* p) {
    uint32_t a;
    asm("{ .reg .u64 t; cvta.to.shared.u64 t, %1; cvt.u32.u64 %0, t; }" : "=r"(a) : "l"(p));
    return a;
}
#define CP_ASYNC16(dst, src) \
    asm volatile("cp.async.cg.shared.global [%0], [%1], 16;" :: "r"(dst), "l"(src))
#define CP_COMMIT() asm volatile("cp.async.commit_group;" ::: "memory")
#define CP_WAIT0()  asm volatile("cp.async.wait_group 0;" ::: "memory")
#define CP_WAIT1()  asm volatile("cp.async.wait_group 1;" ::: "memory")
#define CP_WAIT3()  asm volatile("cp.async.wait_group 3;" ::: "memory")

__device__ __forceinline__ void ldm_x4(uint32_t* r, uint32_t addr) {
    asm volatile("ldmatrix.sync.aligned.m8n8.x4.shared.b16 {%0,%1,%2,%3}, [%4];"
        : "=r"(r[0]), "=r"(r[1]), "=r"(r[2]), "=r"(r[3]) : "r"(addr));
}
__device__ __forceinline__ void ldm_x4_t(uint32_t* r, uint32_t addr) {
    asm volatile("ldmatrix.sync.aligned.m8n8.x4.trans.shared.b16 {%0,%1,%2,%3}, [%4];"
        : "=r"(r[0]), "=r"(r[1]), "=r"(r[2]), "=r"(r[3]) : "r"(addr));
}
__device__ __forceinline__ void mma_bf16(float* c, const uint32_t* a, const uint32_t* b) {
    asm volatile(
        "mma.sync.aligned.m16n8k16.row.col.f32.bf16.bf16.f32 "
        "{%0,%1,%2,%3}, {%4,%5,%6,%7}, {%8,%9}, {%0,%1,%2,%3};"
        : "+f"(c[0]), "+f"(c[1]), "+f"(c[2]), "+f"(c[3])
        : "r"(a[0]), "r"(a[1]), "r"(a[2]), "r"(a[3]), "r"(b[0]), "r"(b[1]));
}
__device__ __forceinline__ uint32_t packbf(float lo, float hi) {
    uint32_t d;
    asm("cvt.rn.bf16x2.f32 %0, %1, %2;" : "=r"(d) : "f"(hi), "f"(lo));
    return d;
}

// ============================================================
// bf16x3 HMMA GEMM: C[M,N] = A[M,3584] @ W[N,3584]^T (+bias)
// CTA 128x128, BK=16, 4-stage cp.async (loads issued 3 chunks
// ahead, BEFORE the wait), 8 warps of 64x32. 2 CTAs/SM.
// Per-stage: Ahi/Alo/Bhi/Blo, each 128 rows x 48B (32B data +
// 16B pad; pitch is a multiple of 16 -> ldmatrix aligned,
// 12-bank stride -> conflict-free phases)
// ============================================================
#define ROWB      48
#define TEN_BYTES (128 * ROWB)        // 6144
#define STG_BYTES (4 * TEN_BYTES)     // 24576
#define GEMM_SMEM (4 * STG_BYTES)     // 98304

__device__ __forceinline__ void g_load_chunk(
    uint32_t smb, int stage, int c,
    const __nv_bfloat16* __restrict__ Ahi, const __nv_bfloat16* __restrict__ Alo,
    const __nv_bfloat16* __restrict__ Bhi, const __nv_bfloat16* __restrict__ Blo,
    int m0, int n0)
{
    const int tid = threadIdx.x;
    const int k0 = c * BK;
    const uint32_t sb = smb + stage * STG_BYTES;
#pragma unroll
    for (int it = 0; it < 4; it++) {
        const int idx = it * 256 + tid;      // 0..1023 16B units
        const int tz  = idx >> 8;            // 0=Ahi 1=Alo 2=Bhi 3=Blo
        const int rem = idx & 255;
        const int row = rem >> 1;            // 0..127
        const int u   = rem & 1;             // 16B unit within 32B row
        const __nv_bfloat16* src;
        if (tz == 0)      src = Ahi + (size_t)(m0 + row) * KDIM + k0 + u * 8;
        else if (tz == 1) src = Alo + (size_t)(m0 + row) * KDIM + k0 + u * 8;
        else if (tz == 2) src = Bhi + (size_t)(n0 + row) * KDIM + k0 + u * 8;
        else              src = Blo + (size_t)(n0 + row) * KDIM + k0 + u * 8;
        CP_ASYNC16(sb + tz * TEN_BYTES + row * ROWB + u * 16, src);
    }
}

__global__ void __launch_bounds__(256, 2) gemm_tc(
    const __nv_bfloat16* __restrict__ Ahi, const __nv_bfloat16* __restrict__ Alo,
    const __nv_bfloat16* __restrict__ Bhi, const __nv_bfloat16* __restrict__ Blo,
    const float* __restrict__ bias, float* __restrict__ C, int N)
{
    extern __shared__ __align__(128) char sm[];
    const uint32_t smb = smem_u32(sm);
    const int tid  = threadIdx.x;
    const int wid  = tid >> 5;
    const int lane = tid & 31;
    const int wm   = wid & 1;        // 64-row slab
    const int wn   = wid >> 1;       // 32-col slab
    const int n0 = blockIdx.x * 128;
    const int m0 = blockIdx.y * 128;

    float acc[4][4][4];
#pragma unroll
    for (int i = 0; i < 4; i++)
#pragma unroll
        for (int j = 0; j < 4; j++)
#pragma unroll
            for (int r = 0; r < 4; r++) acc[i][j][r] = 0.f;

    const int lrow8 = (lane & 7) + ((lane >> 3) & 1) * 8;
    const int lk16  = ((lane >> 4) & 1) * 16;
    const int brow  = (lane & 7);
    const int bk16  = ((lane >> 3) & 1) * 16;
    const int bnf   = ((lane >> 4) & 1) * 8;

    // prologue: preload chunks 0..2
    g_load_chunk(smb, 0, 0, Ahi, Alo, Bhi, Blo, m0, n0); CP_COMMIT();
    g_load_chunk(smb, 1, 1, Ahi, Alo, Bhi, Blo, m0, n0); CP_COMMIT();
    g_load_chunk(smb, 2, 2, Ahi, Alo, Bhi, Blo, m0, n0); CP_COMMIT();

    for (int c = 0; c < NCHUNK; c++) {
        // issue chunk c+3 first (its stage was freed at end of iter c-1)
        if (c + 3 < NCHUNK)
            g_load_chunk(smb, (c + 3) & 3, c + 3, Ahi, Alo, Bhi, Blo, m0, n0);
        CP_COMMIT();
        CP_WAIT3();            // chunk c's group is complete
        __syncthreads();

        const uint32_t stg = smb + (c & 3) * STG_BYTES;
        const uint32_t aHiB = stg + (wm * 64) * ROWB;
        const uint32_t aLoB = stg + TEN_BYTES + (wm * 64) * ROWB;
        const uint32_t bHiB = stg + 2 * TEN_BYTES + (wn * 32) * ROWB;
        const uint32_t bLoB = stg + 3 * TEN_BYTES + (wn * 32) * ROWB;

        uint32_t ah[4][4], al[4][4];
#pragma unroll
        for (int mf = 0; mf < 4; mf++) {
            const uint32_t off = (mf * 16 + lrow8) * ROWB + lk16;
            ldm_x4(ah[mf], aHiB + off);
            ldm_x4(al[mf], aLoB + off);
        }
#pragma unroll
        for (int nfp = 0; nfp < 2; nfp++) {
            uint32_t bh[4], bl[4];
            const uint32_t boff = (nfp * 16 + bnf + brow) * ROWB + bk16;
            ldm_x4(bh, bHiB + boff);
            ldm_x4(bl, bLoB + boff);
#pragma unroll
            for (int mf = 0; mf < 4; mf++) {
                mma_bf16(acc[mf][nfp * 2 + 0], ah[mf], bh + 0);
                mma_bf16(acc[mf][nfp * 2 + 0], ah[mf], bl + 0);
                mma_bf16(acc[mf][nfp * 2 + 0], al[mf], bh + 0);
                mma_bf16(acc[mf][nfp * 2 + 1], ah[mf], bh + 2);
                mma_bf16(acc[mf][nfp * 2 + 1], ah[mf], bl + 2);
                mma_bf16(acc[mf][nfp * 2 + 1], al[mf], bh + 2);
            }
        }
        __syncthreads();       // stage (c+4)&3 == (c)&3 overwritten next iter
    }
    CP_WAIT0();

    const int gtag = lane >> 2;
    const int tig  = lane & 3;
#pragma unroll
    for (int mf = 0; mf < 4; mf++) {
#pragma unroll
        for (int nf = 0; nf < 4; nf++) {
            const int col = n0 + wn * 32 + nf * 8 + tig * 2;
            float b0 = 0.f, b1 = 0.f;
            if (bias) { b0 = bias[col]; b1 = bias[col + 1]; }
            const int r0 = m0 + wm * 64 + mf * 16 + gtag;
            float2 v0 = make_float2(acc[mf][nf][0] + b0, acc[mf][nf][1] + b1);
            float2 v1 = make_float2(acc[mf][nf][2] + b0, acc[mf][nf][3] + b1);
            *reinterpret_cast<float2*>(C + (size_t)r0 * N + col) = v0;
            *reinterpret_cast<float2*>(C + (size_t)(r0 + 8) * N + col) = v1;
        }
    }
}

// ============================================================
// fp32 -> bf16 hi/lo split
// ============================================================
__global__ void split_bf16(const float* __restrict__ x,
                           __nv_bfloat16* __restrict__ hi,
                           __nv_bfloat16* __restrict__ lo, int n4)
{
    for (int i = blockIdx.x * blockDim.x + threadIdx.x; i < n4; i += gridDim.x * blockDim.x) {
        const float4 v = reinterpret_cast<const float4*>(x)[i];
        __nv_bfloat16 h0 = __float2bfloat16(v.x), h1 = __float2bfloat16(v.y);
        __nv_bfloat16 h2 = __float2bfloat16(v.z), h3 = __float2bfloat16(v.w);
        __nv_bfloat16 l0 = __float2bfloat16(v.x - __bfloat162float(h0));
        __nv_bfloat16 l1 = __float2bfloat16(v.y - __bfloat162float(h1));
        __nv_bfloat16 l2 = __float2bfloat16(v.z - __bfloat162float(h2));
        __nv_bfloat16 l3 = __float2bfloat16(v.w - __bfloat162float(h3));
        __nv_bfloat162* hp = reinterpret_cast<__nv_bfloat162*>(hi) + i * 2;
        __nv_bfloat162* lp = reinterpret_cast<__nv_bfloat162*>(lo) + i * 2;
        hp[0] = __nv_bfloat162(h0, h1); hp[1] = __nv_bfloat162(h2, h3);
        lp[0] = __nv_bfloat162(l0, l1); lp[1] = __nv_bfloat162(l2, l3);
    }
}

// ============================================================
// RoPE + cache scatter + bf16 hi/lo emission of q/k/v
// ============================================================
__global__ void rope_scatter(float* __restrict__ qkv,
                             const int* __restrict__ positions,
                             const int* __restrict__ slot_map,
                             float* __restrict__ kc,
                             float* __restrict__ vc,
                             __nv_bfloat16* __restrict__ qhi, __nv_bfloat16* __restrict__ qlo,
                             __nv_bfloat16* __restrict__ khi, __nv_bfloat16* __restrict__ klo,
                             __nv_bfloat16* __restrict__ vhi, __nv_bfloat16* __restrict__ vlo)
{
    const int t = blockIdx.x;
    const int b = t / SEQ;
    const int s = t % SEQ;
    const float pos = (float)positions[t];
    float* base_t = qkv + (size_t)t * QKV_OUT;

    for (int idx = threadIdx.x; idx < (NH + NKV) * 64; idx += blockDim.x) {
        const int head = idx >> 6;
        const int j    = idx & 63;
        const float inv = __expf(-(float)j * RLN10K);
        float sn, cs;
        sincosf(pos * inv, &sn, &cs);
        float* p = base_t + head * HD;
        const float x1 = p[j];
        const float x2 = p[j + 64];
        const float sc = (head < NH) ? SCALE : 1.0f;
        p[j]      = (x1 * cs - x2 * sn) * sc;
        p[j + 64] = (x2 * cs + x1 * sn) * sc;
    }
    __syncthreads();

    const int slot = slot_map[t];
    for (int idx = threadIdx.x; idx < 2 * NKV * HD; idx += blockDim.x) {
        if (idx < NKV * HD)
            kc[(size_t)slot * NKV * HD + idx] = base_t[NH * HD + idx];
        else
            vc[(size_t)slot * NKV * HD + (idx - NKV*HD)] = base_t[(NH + NKV) * HD + (idx - NKV*HD)];
    }
    for (int idx = threadIdx.x; idx < NH * HD; idx += blockDim.x) {
        const float f = base_t[idx];
        const __nv_bfloat16 h = __float2bfloat16(f);
        qhi[(size_t)t * NH * HD + idx] = h;
        qlo[(size_t)t * NH * HD + idx] = __float2bfloat16(f - __bfloat162float(h));
    }
    for (int idx = threadIdx.x; idx < 2 * NKV * HD; idx += blockDim.x) {
        const int which = idx >= NKV * HD;
        const int i = idx - which * NKV * HD;
        const int kvh = i >> 7;
        const int d = i & 127;
        const float f = base_t[(NH + (which ? NKV : 0)) * HD + i];
        const __nv_bfloat16 h = __float2bfloat16(f);
        const __nv_bfloat16 l = __float2bfloat16(f - __bfloat162float(h));
        const size_t off = ((size_t)(b * NKV + kvh) * SEQ + s) * HD + d;
        if (which) { vhi[off] = h; vlo[off] = l; }
        else       { khi[off] = h; klo[off] = l; }
    }
}

// ============================================================
// Tensor-core flash attention (bf16x3); epilogue writes ctx
// directly as bf16 hi/lo for the output GEMM.
// ============================================================
#define AP       272
#define QSMEM    (2 * 128 * AP)
#define KVSTG    (4 * 64 * AP)
#define ATTN_SMEM (QSMEM + 2 * KVSTG)

__device__ __forceinline__ void a_load_kv(
    uint32_t smb, int stage, int kt, int bkv,
    const __nv_bfloat16* __restrict__ khi, const __nv_bfloat16* __restrict__ klo,
    const __nv_bfloat16* __restrict__ vhi, const __nv_bfloat16* __restrict__ vlo)
{
    const int tid = threadIdx.x;
#pragma unroll
    for (int it = 0; it < 16; it++) {
        const int idx = it * 256 + tid;
        const int tz  = idx >> 10;
        const int rem = idx & 1023;
        const int row = rem >> 4;
        const int u   = rem & 15;
        const __nv_bfloat16* src;
        if (tz == 0)      src = khi;
        else if (tz == 1) src = klo;
        else if (tz == 2) src = vhi;
        else              src = vlo;
        src += ((size_t)bkv * SEQ + kt * 64 + row) * HD + u * 8;
        const uint32_t dst = smb + QSMEM + stage * KVSTG + tz * (64 * AP) + row * AP + u * 16;
        CP_ASYNC16(dst, src);
    }
}

__global__ void __launch_bounds__(256, 1) attn_tc(
    const __nv_bfloat16* __restrict__ qhi, const __nv_bfloat16* __restrict__ qlo,
    const __nv_bfloat16* __restrict__ khi, const __nv_bfloat16* __restrict__ klo,
    const __nv_bfloat16* __restrict__ vhi, const __nv_bfloat16* __restrict__ vlo,
    __nv_bfloat16* __restrict__ chi, __nv_bfloat16* __restrict__ clo)
{
    extern __shared__ __align__(128) char sm[];
    const uint32_t smb = smem_u32(sm);
    const int tid  = threadIdx.x;
    const int wid  = tid >> 5;
    const int lane = tid & 31;
    const int qb = blockIdx.x;
    const int h  = blockIdx.y;
    const int b  = blockIdx.z;
    const int q0 = qb * 128;
    const int bkv = b * NKV + h / GROUP;
    const int nkt = 2 * (qb + 1);

#pragma unroll
    for (int it = 0; it < 16; it++) {
        const int idx = it * 256 + tid;
        const int tz  = idx >> 11;
        const int rem = idx & 2047;
        const int row = rem >> 4;
        const int u   = rem & 15;
        const __nv_bfloat16* src = (tz ? qlo : qhi)
            + (size_t)(b * SEQ + q0 + row) * (NH * HD) + h * HD + u * 8;
        const uint32_t dst = smb + tz * (128 * AP) + row * AP + u * 16;
        CP_ASYNC16(dst, src);
    }
    a_load_kv(smb, 0, 0, bkv, khi, klo, vhi, vlo);
    CP_COMMIT();

    float m0 = -1e30f, m1 = -1e30f, l0 = 0.f, l1 = 0.f;
    float o[16][4];
#pragma unroll
    for (int i = 0; i < 16; i++)
#pragma unroll
        for (int j = 0; j < 4; j++) o[i][j] = 0.f;

    const int lrow8 = (lane & 7) + ((lane >> 3) & 1) * 8;
    const int lk16  = ((lane >> 4) & 1) * 16;
    const int brow  = (lane & 7);
    const int bk16  = ((lane >> 3) & 1) * 16;
    const int bnf   = ((lane >> 4) & 1) * 8;
    const int rloc  = wid * 16 + (lane >> 2);
    const int rg0   = q0 + rloc;

    for (int kt = 0; kt < nkt; kt++) {
        if (kt + 1 < nkt) {
            a_load_kv(smb, (kt + 1) & 1, kt + 1, bkv, khi, klo, vhi, vlo);
            CP_COMMIT();
            CP_WAIT1();
        } else {
            CP_WAIT0();
        }
        __syncthreads();

        const uint32_t stg = smb + QSMEM + (kt & 1) * KVSTG;
        const uint32_t Khi_s = stg;
        const uint32_t Klo_s = stg + 64 * AP;
        const uint32_t Vhi_s = stg + 128 * AP;
        const uint32_t Vlo_s = stg + 192 * AP;

        float sf[8][4];
#pragma unroll
        for (int i = 0; i < 8; i++)
#pragma unroll
            for (int j = 0; j < 4; j++) sf[i][j] = 0.f;

#pragma unroll
        for (int ks = 0; ks < 8; ks++) {
            const int kb = ks * 32;
            uint32_t ah[4], al[4];
            const uint32_t qoff = (wid * 16 + lrow8) * AP + kb + lk16;
            ldm_x4(ah, smb + qoff);
            ldm_x4(al, smb + 128 * AP + qoff);
#pragma unroll
            for (int nfp = 0; nfp < 4; nfp++) {
                uint32_t bh[4], bl[4];
                const uint32_t boff = (nfp * 16 + bnf + brow) * AP + kb + bk16;
                ldm_x4(bh, Khi_s + boff);
                ldm_x4(bl, Klo_s + boff);
                mma_bf16(sf[nfp * 2 + 0], ah, bh + 0);
                mma_bf16(sf[nfp * 2 + 0], ah, bl + 0);
                mma_bf16(sf[nfp * 2 + 0], al, bh + 0);
                mma_bf16(sf[nfp * 2 + 1], ah, bh + 2);
                mma_bf16(sf[nfp * 2 + 1], ah, bl + 2);
                mma_bf16(sf[nfp * 2 + 1], al, bh + 2);
            }
        }

        const int k0 = kt * 64;
        if (k0 + 63 > rg0) {
#pragma unroll
            for (int nf = 0; nf < 8; nf++) {
                const int cb = k0 + nf * 8 + (lane & 3) * 2;
                if (cb + 0 > rg0)     sf[nf][0] = -1e30f;
                if (cb + 1 > rg0)     sf[nf][1] = -1e30f;
                if (cb + 0 > rg0 + 8) sf[nf][2] = -1e30f;
                if (cb + 1 > rg0 + 8) sf[nf][3] = -1e30f;
            }
        }

        float mx0 = -1e30f, mx1 = -1e30f;
#pragma unroll
        for (int nf = 0; nf < 8; nf++) {
            mx0 = fmaxf(mx0, fmaxf(sf[nf][0], sf[nf][1]));
            mx1 = fmaxf(mx1, fmaxf(sf[nf][2], sf[nf][3]));
        }
        mx0 = fmaxf(mx0, __shfl_xor_sync(0xffffffffu, mx0, 1));
        mx0 = fmaxf(mx0, __shfl_xor_sync(0xffffffffu, mx0, 2));
        mx1 = fmaxf(mx1, __shfl_xor_sync(0xffffffffu, mx1, 1));
        mx1 = fmaxf(mx1, __shfl_xor_sync(0xffffffffu, mx1, 2));

        const float mn0 = fmaxf(m0, mx0);
        const float mn1 = fmaxf(m1, mx1);
        const float a0 = __expf(m0 - mn0);
        const float a1 = __expf(m1 - mn1);
        m0 = mn0; m1 = mn1;

        float rs0 = 0.f, rs1 = 0.f;
#pragma unroll
        for (int nf = 0; nf < 8; nf++) {
            sf[nf][0] = __expf(sf[nf][0] - mn0); rs0 += sf[nf][0];
            sf[nf][1] = __expf(sf[nf][1] - mn0); rs0 += sf[nf][1];
            sf[nf][2] = __expf(sf[nf][2] - mn1); rs1 += sf[nf][2];
            sf[nf][3] = __expf(sf[nf][3] - mn1); rs1 += sf[nf][3];
        }
        rs0 += __shfl_xor_sync(0xffffffffu, rs0, 1);
        rs0 += __shfl_xor_sync(0xffffffffu, rs0, 2);
        rs1 += __shfl_xor_sync(0xffffffffu, rs1, 1);
        rs1 += __shfl_xor_sync(0xffffffffu, rs1, 2);
        l0 = l0 * a0 + rs0;
        l1 = l1 * a1 + rs1;

#pragma unroll
        for (int i = 0; i < 16; i++) {
            o[i][0] *= a0; o[i][1] *= a0; o[i][2] *= a1; o[i][3] *= a1;
        }

#pragma unroll
        for (int kk = 0; kk < 4; kk++) {
            uint32_t ph[4], pl[4];
            float hfr[8], lfr[8];
#pragma unroll
            for (int e = 0; e < 4; e++) {
                float f0 = sf[2 * kk][e];
                float f1 = sf[2 * kk + 1][e];
                float h0 = __bfloat162float(__float2bfloat16(f0));
                float h1 = __bfloat162float(__float2bfloat16(f1));
                hfr[e] = h0; hfr[4 + e] = h1;
                lfr[e] = f0 - h0; lfr[4 + e] = f1 - h1;
            }
            ph[0] = packbf(hfr[0], hfr[1]); ph[1] = packbf(hfr[2], hfr[3]);
            ph[2] = packbf(hfr[4], hfr[5]); ph[3] = packbf(hfr[6], hfr[7]);
            pl[0] = packbf(lfr[0], lfr[1]); pl[1] = packbf(lfr[2], lfr[3]);
            pl[2] = packbf(lfr[4], lfr[5]); pl[3] = packbf(lfr[6], lfr[7]);

#pragma unroll
            for (int db = 0; db < 8; db++) {
                uint32_t vh[4], vl[4];
                const uint32_t voff = (kk * 16 + (lane & 15)) * AP
                                    + (db * 16 + ((lane >> 4) & 1) * 8) * 2;
                ldm_x4_t(vh, Vhi_s + voff);
                ldm_x4_t(vl, Vlo_s + voff);
                mma_bf16(o[db * 2 + 0], ph, vh + 0);
                mma_bf16(o[db * 2 + 0], pl, vh + 0);
                mma_bf16(o[db * 2 + 0], ph, vl + 0);
                mma_bf16(o[db * 2 + 1], ph, vh + 2);
                mma_bf16(o[db * 2 + 1], pl, vh + 2);
                mma_bf16(o[db * 2 + 1], ph, vl + 2);
            }
        }
        __syncthreads();
    }

    const float rv0 = 1.0f / l0;
    const float rv1 = 1.0f / l1;
    const size_t t0 = (size_t)(b * SEQ + rg0);
    const size_t t1 = t0 + 8;
#pragma unroll
    for (int nf = 0; nf < 16; nf++) {
        const int col = h * HD + nf * 8 + (lane & 3) * 2;
        float f0 = o[nf][0] * rv0, f1 = o[nf][1] * rv0;
        float f2 = o[nf][2] * rv1, f3 = o[nf][3] * rv1;
        __nv_bfloat16 h0 = __float2bfloat16(f0), h1 = __float2bfloat16(f1);
        __nv_bfloat16 h2 = __float2bfloat16(f2), h3 = __float2bfloat16(f3);
        *reinterpret_cast<__nv_bfloat162*>(chi + t0 * (NH * HD) + col) = __nv_bfloat162(h0, h1);
        *reinterpret_cast<__nv_bfloat162*>(chi + t1 * (NH * HD) + col) = __nv_bfloat162(h2, h3);
        *reinterpret_cast<__nv_bfloat162*>(clo + t0 * (NH * HD) + col) =
            __nv_bfloat162(__float2bfloat16(f0 - __bfloat162float(h0)),
                           __float2bfloat16(f1 - __bfloat162float(h1)));
        *reinterpret_cast<__nv_bfloat162*>(clo + t1 * (NH * HD) + col) =
            __nv_bfloat162(__float2bfloat16(f2 - __bfloat162float(h2)),
                           __float2bfloat16(f3 - __bfloat162float(h3)));
    }
}

// ============================================================
// launch
// ============================================================
extern "C" void kernel_launch(void* const* d_in, const int* in_sizes, int n_in,
                              void* d_out, int out_size)
{
    const int*   positions = (const int*)  d_in[0];
    const float* hidden    = (const float*)d_in[1];
    const float* kv_in     = (const float*)d_in[2];
    const int*   slot_map  = (const int*)  d_in[4];
    const float* w_qkv     = (const float*)d_in[n_in - 3];
    const float* b_qkv     = (const float*)d_in[n_in - 2];
    const float* w_o       = (const float*)d_in[n_in - 1];

    float* out = (float*)d_out;
    float* kc  = out + (size_t)TTOK * H_DIM;
    float* vc  = kc + CACHE_HALF;

    float *qkv_buf;
    __nv_bfloat16 *h_hi, *h_lo, *wq_hi, *wq_lo, *wo_hi, *wo_lo, *c_hi, *c_lo;
    __nv_bfloat16 *q_hi, *q_lo, *k_hi, *k_lo, *v_hi, *v_lo;
    cudaGetSymbolAddress((void**)&qkv_buf, g_qkv);
    cudaGetSymbolAddress((void**)&h_hi, g_h_hi);
    cudaGetSymbolAddress((void**)&h_lo, g_h_lo);
    cudaGetSymbolAddress((void**)&wq_hi, g_wq_hi);
    cudaGetSymbolAddress((void**)&wq_lo, g_wq_lo);
    cudaGetSymbolAddress((void**)&wo_hi, g_wo_hi);
    cudaGetSymbolAddress((void**)&wo_lo, g_wo_lo);
    cudaGetSymbolAddress((void**)&c_hi, g_c_hi);
    cudaGetSymbolAddress((void**)&c_lo, g_c_lo);
    cudaGetSymbolAddress((void**)&q_hi, g_q_hi);
    cudaGetSymbolAddress((void**)&q_lo, g_q_lo);
    cudaGetSymbolAddress((void**)&k_hi, g_k_hi);
    cudaGetSymbolAddress((void**)&k_lo, g_k_lo);
    cudaGetSymbolAddress((void**)&v_hi, g_v_hi);
    cudaGetSymbolAddress((void**)&v_lo, g_v_lo);

    cudaMemcpyAsync(kc, kv_in, (size_t)2 * CACHE_HALF * sizeof(float),
                    cudaMemcpyDeviceToDevice, 0);

    split_bf16<<<2048, 256>>>(hidden, h_hi, h_lo, TTOK * KDIM / 4);
    split_bf16<<<2048, 256>>>(w_qkv, wq_hi, wq_lo, QKV_OUT * KDIM / 4);
    split_bf16<<<2048, 256>>>(w_o, wo_hi, wo_lo, H_DIM * KDIM / 4);

    cudaFuncSetAttribute(gemm_tc, cudaFuncAttributeMaxDynamicSharedMemorySize, GEMM_SMEM);

    // 1) qkv = hidden @ w_qkv^T + b
    gemm_tc<<<dim3(QKV_OUT/128, TTOK/128), 256, GEMM_SMEM>>>(
        h_hi, h_lo, wq_hi, wq_lo, b_qkv, qkv_buf, QKV_OUT);

    // 2) rope + scatter + bf16 emission
    rope_scatter<<<TTOK, 256>>>(qkv_buf, positions, slot_map, kc, vc,
                                q_hi, q_lo, k_hi, k_lo, v_hi, v_lo);

    // 3) tensor-core attention (writes ctx hi/lo directly)
    cudaFuncSetAttribute(attn_tc, cudaFuncAttributeMaxDynamicSharedMemorySize, ATTN_SMEM);
    attn_tc<<<dim3(SEQ/128, NH, BATCH), 256, ATTN_SMEM>>>(
        q_hi, q_lo, k_hi, k_lo, v_hi, v_lo, c_hi, c_lo);

    // 4) out = ctx @ w_o^T
    gemm_tc<<<dim3(H_DIM/128, TTOK/128), 256, GEMM_SMEM>>>(
        c_hi, c_lo, wo_hi, wo_lo, nullptr, out, H_DIM);
}

// round 10
// speedup vs baseline: 1.1685x; 1.1685x over previous
#include <cuda_runtime.h>
#include <cuda_bf16.h>
#include <math.h>
#include <cstdint>

// ---------------- problem constants ----------------
#define H_DIM    3584
#define NH       28
#define NKV      4
#define HD       128
#define GROUP    7
#define BATCH    4
#define SEQ      1024
#define TTOK     4096
#define QKV_OUT  4608
#define NBLK     512
#define BSZ      16
#define CACHE_HALF (NBLK*BSZ*NKV*HD)
#define SCALE    0.08838834764831845f
#define RLN10K   0.1439115671349322f

#define KDIM     3584
#define BK       32
#define NCHUNK   112           // KDIM / BK

// ---------------- scratch ----------------
__device__ float g_qkv[(size_t)TTOK * QKV_OUT];
__device__ __nv_bfloat16 g_h_hi[(size_t)TTOK * KDIM];
__device__ __nv_bfloat16 g_h_lo[(size_t)TTOK * KDIM];
__device__ __nv_bfloat16 g_wq_hi[(size_t)QKV_OUT * KDIM];
__device__ __nv_bfloat16 g_wq_lo[(size_t)QKV_OUT * KDIM];
__device__ __nv_bfloat16 g_wo_hi[(size_t)H_DIM * KDIM];
__device__ __nv_bfloat16 g_wo_lo[(size_t)H_DIM * KDIM];
__device__ __nv_bfloat16 g_c_hi[(size_t)TTOK * KDIM];
__device__ __nv_bfloat16 g_c_lo[(size_t)TTOK * KDIM];
// attention operands (bf16 hi/lo)
__device__ __nv_bfloat16 g_q_hi[(size_t)TTOK * NH * HD];
__device__ __nv_bfloat16 g_q_lo[(size_t)TTOK * NH * HD];
__device__ __nv_bfloat16 g_k_hi[(size_t)BATCH * NKV * SEQ * HD];
__device__ __nv_bfloat16 g_k_lo[(size_t)BATCH * NKV * SEQ * HD];
__device__ __nv_bfloat16 g_v_hi[(size_t)BATCH * NKV * SEQ * HD];
__device__ __nv_bfloat16 g_v_lo[(size_t)BATCH * NKV * SEQ * HD];

// ---------------- helpers ----------------
__device__ __forceinline__ uint32_t smem_u32(const void* p) {
    uint32_t a;
    asm("{ .reg .u64 t; cvta.to.shared.u64 t, %1; cvt.u32.u64 %0, t; }" : "=r"(a) : "l"(p));
    return a;
}
#define CP_ASYNC16(dst, src) \
    asm volatile("cp.async.cg.shared.global [%0], [%1], 16;" :: "r"(dst), "l"(src))
#define CP_COMMIT() asm volatile("cp.async.commit_group;" ::: "memory")
#define CP_WAIT0()  asm volatile("cp.async.wait_group 0;" ::: "memory")
#define CP_WAIT1()  asm volatile("cp.async.wait_group 1;" ::: "memory")
#define CP_WAIT2()  asm volatile("cp.async.wait_group 2;" ::: "memory")

__device__ __forceinline__ void ldm_x4(uint32_t* r, uint32_t addr) {
    asm volatile("ldmatrix.sync.aligned.m8n8.x4.shared.b16 {%0,%1,%2,%3}, [%4];"
        : "=r"(r[0]), "=r"(r[1]), "=r"(r[2]), "=r"(r[3]) : "r"(addr));
}
__device__ __forceinline__ void ldm_x4_t(uint32_t* r, uint32_t addr) {
    asm volatile("ldmatrix.sync.aligned.m8n8.x4.trans.shared.b16 {%0,%1,%2,%3}, [%4];"
        : "=r"(r[0]), "=r"(r[1]), "=r"(r[2]), "=r"(r[3]) : "r"(addr));
}
__device__ __forceinline__ void mma_bf16(float* c, const uint32_t* a, const uint32_t* b) {
    asm volatile(
        "mma.sync.aligned.m16n8k16.row.col.f32.bf16.bf16.f32 "
        "{%0,%1,%2,%3}, {%4,%5,%6,%7}, {%8,%9}, {%0,%1,%2,%3};"
        : "+f"(c[0]), "+f"(c[1]), "+f"(c[2]), "+f"(c[3])
        : "r"(a[0]), "r"(a[1]), "r"(a[2]), "r"(a[3]), "r"(b[0]), "r"(b[1]));
}
__device__ __forceinline__ uint32_t packbf(float lo, float hi) {
    uint32_t d;
    asm("cvt.rn.bf16x2.f32 %0, %1, %2;" : "=r"(d) : "f"(hi), "f"(lo));
    return d;
}

// ============================================================
// bf16x3 HMMA GEMM: C[M,N] = A[M,3584] @ W[N,3584]^T (+bias)
// CTA 128x128, BK=32, 3-stage cp.async (loads for c+2 issued
// BEFORE waiting on c), 8 warps of 64x32, 2 CTAs/SM.
// No padding: 64B rows with XOR swizzle u' = u ^ ((row>>1)&3)
// (16B units) -> conflict-free ldmatrix and cp.async stores.
// Stage: Ahi/Alo/Bhi/Blo x 8192B = 32 KB; 3 stages = 96 KB.
// ============================================================
#define TEN_BYTES 8192                 // 128 rows x 64 B
#define STG_BYTES (4 * TEN_BYTES)      // 32768
#define GEMM_SMEM (3 * STG_BYTES)      // 98304

__device__ __forceinline__ uint32_t gsw(int row, int u) {
    return (uint32_t)(row * 64 + ((u ^ ((row >> 1) & 3)) << 4));
}

__device__ __forceinline__ void g_load_chunk(
    uint32_t smb, int stage, int c,
    const __nv_bfloat16* __restrict__ Ahi, const __nv_bfloat16* __restrict__ Alo,
    const __nv_bfloat16* __restrict__ Bhi, const __nv_bfloat16* __restrict__ Blo,
    int m0, int n0)
{
    const int tid = threadIdx.x;
    const int k0 = c * BK;
    const uint32_t sb = smb + stage * STG_BYTES;
#pragma unroll
    for (int it = 0; it < 8; it++) {
        const int idx = it * 256 + tid;      // 0..2047 16B units
        const int tz  = idx >> 9;            // 0=Ahi 1=Alo 2=Bhi 3=Blo
        const int rem = idx & 511;
        const int row = rem >> 2;            // 0..127
        const int u   = rem & 3;             // 16B unit within 64B row
        const __nv_bfloat16* src;
        if (tz == 0)      src = Ahi + (size_t)(m0 + row) * KDIM + k0 + u * 8;
        else if (tz == 1) src = Alo + (size_t)(m0 + row) * KDIM + k0 + u * 8;
        else if (tz == 2) src = Bhi + (size_t)(n0 + row) * KDIM + k0 + u * 8;
        else              src = Blo + (size_t)(n0 + row) * KDIM + k0 + u * 8;
        CP_ASYNC16(sb + tz * TEN_BYTES + gsw(row, u), src);
    }
}

__global__ void __launch_bounds__(256, 2) gemm_tc(
    const __nv_bfloat16* __restrict__ Ahi, const __nv_bfloat16* __restrict__ Alo,
    const __nv_bfloat16* __restrict__ Bhi, const __nv_bfloat16* __restrict__ Blo,
    const float* __restrict__ bias, float* __restrict__ C, int N)
{
    extern __shared__ __align__(128) char sm[];
    const uint32_t smb = smem_u32(sm);
    const int tid  = threadIdx.x;
    const int wid  = tid >> 5;
    const int lane = tid & 31;
    const int wm   = wid & 1;        // 64-row slab
    const int wn   = wid >> 1;       // 32-col slab
    const int n0 = blockIdx.x * 128;
    const int m0 = blockIdx.y * 128;

    float acc[4][4][4];
#pragma unroll
    for (int i = 0; i < 4; i++)
#pragma unroll
        for (int j = 0; j < 4; j++)
#pragma unroll
            for (int r = 0; r < 4; r++) acc[i][j][r] = 0.f;

    const int lrow8 = (lane & 7) + ((lane >> 3) & 1) * 8;   // A row-in-frag
    const int lkbit = (lane >> 4) & 1;                      // A k16 select
    const int brow  = (lane & 7);                           // B row-in-frag
    const int bkbit = (lane >> 3) & 1;                      // B k16 select
    const int bnf   = ((lane >> 4) & 1) * 8;                // B second n-frag

    // prologue: preload chunks 0,1
    g_load_chunk(smb, 0, 0, Ahi, Alo, Bhi, Blo, m0, n0); CP_COMMIT();
    g_load_chunk(smb, 1, 1, Ahi, Alo, Bhi, Blo, m0, n0); CP_COMMIT();

    int stage = 0;
    for (int c = 0; c < NCHUNK; c++) {
        // issue chunk c+2 into the stage freed at end of last iter
        if (c + 2 < NCHUNK)
            g_load_chunk(smb, (c + 2) % 3, c + 2, Ahi, Alo, Bhi, Blo, m0, n0);
        CP_COMMIT();
        CP_WAIT2();            // chunk c's group complete
        __syncthreads();

        const uint32_t stg = smb + stage * STG_BYTES;
        const uint32_t aHiB = stg;
        const uint32_t aLoB = stg + TEN_BYTES;
        const uint32_t bHiB = stg + 2 * TEN_BYTES;
        const uint32_t bLoB = stg + 3 * TEN_BYTES;

#pragma unroll
        for (int ks = 0; ks < 2; ks++) {
            uint32_t ah[4][4], al[4][4];
#pragma unroll
            for (int mf = 0; mf < 4; mf++) {
                const int arow = wm * 64 + mf * 16 + lrow8;
                const uint32_t off = gsw(arow, ks * 2 + lkbit);
                ldm_x4(ah[mf], aHiB + off);
                ldm_x4(al[mf], aLoB + off);
            }
#pragma unroll
            for (int nfp = 0; nfp < 2; nfp++) {
                uint32_t bh[4], bl[4];
                const int brw = wn * 32 + nfp * 16 + bnf + brow;
                const uint32_t boff = gsw(brw, ks * 2 + bkbit);
                ldm_x4(bh, bHiB + boff);
                ldm_x4(bl, bLoB + boff);
#pragma unroll
                for (int mf = 0; mf < 4; mf++) {
                    mma_bf16(acc[mf][nfp * 2 + 0], ah[mf], bh + 0);
                    mma_bf16(acc[mf][nfp * 2 + 0], ah[mf], bl + 0);
                    mma_bf16(acc[mf][nfp * 2 + 0], al[mf], bh + 0);
                    mma_bf16(acc[mf][nfp * 2 + 1], ah[mf], bh + 2);
                    mma_bf16(acc[mf][nfp * 2 + 1], ah[mf], bl + 2);
                    mma_bf16(acc[mf][nfp * 2 + 1], al[mf], bh + 2);
                }
            }
        }
        __syncthreads();       // stage gets overwritten by iter c+1's load
        stage = (stage + 1) % 3;
    }
    CP_WAIT0();

    const int gtag = lane >> 2;
    const int tig  = lane & 3;
#pragma unroll
    for (int mf = 0; mf < 4; mf++) {
#pragma unroll
        for (int nf = 0; nf < 4; nf++) {
            const int col = n0 + wn * 32 + nf * 8 + tig * 2;
            float b0 = 0.f, b1 = 0.f;
            if (bias) { b0 = bias[col]; b1 = bias[col + 1]; }
            const int r0 = m0 + wm * 64 + mf * 16 + gtag;
            float2 v0 = make_float2(acc[mf][nf][0] + b0, acc[mf][nf][1] + b1);
            float2 v1 = make_float2(acc[mf][nf][2] + b0, acc[mf][nf][3] + b1);
            *reinterpret_cast<float2*>(C + (size_t)r0 * N + col) = v0;
            *reinterpret_cast<float2*>(C + (size_t)(r0 + 8) * N + col) = v1;
        }
    }
}

// ============================================================
// fp32 -> bf16 hi/lo split
// ============================================================
__global__ void split_bf16(const float* __restrict__ x,
                           __nv_bfloat16* __restrict__ hi,
                           __nv_bfloat16* __restrict__ lo, int n4)
{
    for (int i = blockIdx.x * blockDim.x + threadIdx.x; i < n4; i += gridDim.x * blockDim.x) {
        const float4 v = reinterpret_cast<const float4*>(x)[i];
        __nv_bfloat16 h0 = __float2bfloat16(v.x), h1 = __float2bfloat16(v.y);
        __nv_bfloat16 h2 = __float2bfloat16(v.z), h3 = __float2bfloat16(v.w);
        __nv_bfloat16 l0 = __float2bfloat16(v.x - __bfloat162float(h0));
        __nv_bfloat16 l1 = __float2bfloat16(v.y - __bfloat162float(h1));
        __nv_bfloat16 l2 = __float2bfloat16(v.z - __bfloat162float(h2));
        __nv_bfloat16 l3 = __float2bfloat16(v.w - __bfloat162float(h3));
        __nv_bfloat162* hp = reinterpret_cast<__nv_bfloat162*>(hi) + i * 2;
        __nv_bfloat162* lp = reinterpret_cast<__nv_bfloat162*>(lo) + i * 2;
        hp[0] = __nv_bfloat162(h0, h1); hp[1] = __nv_bfloat162(h2, h3);
        lp[0] = __nv_bfloat162(l0, l1); lp[1] = __nv_bfloat162(l2, l3);
    }
}

// ============================================================
// RoPE + cache scatter + bf16 hi/lo emission of q/k/v
// ============================================================
__global__ void rope_scatter(float* __restrict__ qkv,
                             const int* __restrict__ positions,
                             const int* __restrict__ slot_map,
                             float* __restrict__ kc,
                             float* __restrict__ vc,
                             __nv_bfloat16* __restrict__ qhi, __nv_bfloat16* __restrict__ qlo,
                             __nv_bfloat16* __restrict__ khi, __nv_bfloat16* __restrict__ klo,
                             __nv_bfloat16* __restrict__ vhi, __nv_bfloat16* __restrict__ vlo)
{
    const int t = blockIdx.x;
    const int b = t / SEQ;
    const int s = t % SEQ;
    const float pos = (float)positions[t];
    float* base_t = qkv + (size_t)t * QKV_OUT;

    for (int idx = threadIdx.x; idx < (NH + NKV) * 64; idx += blockDim.x) {
        const int head = idx >> 6;
        const int j    = idx & 63;
        const float inv = __expf(-(float)j * RLN10K);
        float sn, cs;
        sincosf(pos * inv, &sn, &cs);
        float* p = base_t + head * HD;
        const float x1 = p[j];
        const float x2 = p[j + 64];
        const float sc = (head < NH) ? SCALE : 1.0f;
        p[j]      = (x1 * cs - x2 * sn) * sc;
        p[j + 64] = (x2 * cs + x1 * sn) * sc;
    }
    __syncthreads();

    const int slot = slot_map[t];
    for (int idx = threadIdx.x; idx < 2 * NKV * HD; idx += blockDim.x) {
        if (idx < NKV * HD)
            kc[(size_t)slot * NKV * HD + idx] = base_t[NH * HD + idx];
        else
            vc[(size_t)slot * NKV * HD + (idx - NKV*HD)] = base_t[(NH + NKV) * HD + (idx - NKV*HD)];
    }
    for (int idx = threadIdx.x; idx < NH * HD; idx += blockDim.x) {
        const float f = base_t[idx];
        const __nv_bfloat16 h = __float2bfloat16(f);
        qhi[(size_t)t * NH * HD + idx] = h;
        qlo[(size_t)t * NH * HD + idx] = __float2bfloat16(f - __bfloat162float(h));
    }
    for (int idx = threadIdx.x; idx < 2 * NKV * HD; idx += blockDim.x) {
        const int which = idx >= NKV * HD;
        const int i = idx - which * NKV * HD;
        const int kvh = i >> 7;
        const int d = i & 127;
        const float f = base_t[(NH + (which ? NKV : 0)) * HD + i];
        const __nv_bfloat16 h = __float2bfloat16(f);
        const __nv_bfloat16 l = __float2bfloat16(f - __bfloat162float(h));
        const size_t off = ((size_t)(b * NKV + kvh) * SEQ + s) * HD + d;
        if (which) { vhi[off] = h; vlo[off] = l; }
        else       { khi[off] = h; klo[off] = l; }
    }
}

// ============================================================
// Tensor-core flash attention (bf16x3); epilogue writes ctx
// directly as bf16 hi/lo for the output GEMM.
// ============================================================
#define AP       272
#define QSMEM    (2 * 128 * AP)
#define KVSTG    (4 * 64 * AP)
#define ATTN_SMEM (QSMEM + 2 * KVSTG)

__device__ __forceinline__ void a_load_kv(
    uint32_t smb, int stage, int kt, int bkv,
    const __nv_bfloat16* __restrict__ khi, const __nv_bfloat16* __restrict__ klo,
    const __nv_bfloat16* __restrict__ vhi, const __nv_bfloat16* __restrict__ vlo)
{
    const int tid = threadIdx.x;
#pragma unroll
    for (int it = 0; it < 16; it++) {
        const int idx = it * 256 + tid;
        const int tz  = idx >> 10;
        const int rem = idx & 1023;
        const int row = rem >> 4;
        const int u   = rem & 15;
        const __nv_bfloat16* src;
        if (tz == 0)      src = khi;
        else if (tz == 1) src = klo;
        else if (tz == 2) src = vhi;
        else              src = vlo;
        src += ((size_t)bkv * SEQ + kt * 64 + row) * HD + u * 8;
        const uint32_t dst = smb + QSMEM + stage * KVSTG + tz * (64 * AP) + row * AP + u * 16;
        CP_ASYNC16(dst, src);
    }
}

__global__ void __launch_bounds__(256, 1) attn_tc(
    const __nv_bfloat16* __restrict__ qhi, const __nv_bfloat16* __restrict__ qlo,
    const __nv_bfloat16* __restrict__ khi, const __nv_bfloat16* __restrict__ klo,
    const __nv_bfloat16* __restrict__ vhi, const __nv_bfloat16* __restrict__ vlo,
    __nv_bfloat16* __restrict__ chi, __nv_bfloat16* __restrict__ clo)
{
    extern __shared__ __align__(128) char sm[];
    const uint32_t smb = smem_u32(sm);
    const int tid  = threadIdx.x;
    const int wid  = tid >> 5;
    const int lane = tid & 31;
    const int qb = blockIdx.x;
    const int h  = blockIdx.y;
    const int b  = blockIdx.z;
    const int q0 = qb * 128;
    const int bkv = b * NKV + h / GROUP;
    const int nkt = 2 * (qb + 1);

#pragma unroll
    for (int it = 0; it < 16; it++) {
        const int idx = it * 256 + tid;
        const int tz  = idx >> 11;
        const int rem = idx & 2047;
        const int row = rem >> 4;
        const int u   = rem & 15;
        const __nv_bfloat16* src = (tz ? qlo : qhi)
            + (size_t)(b * SEQ + q0 + row) * (NH * HD) + h * HD + u * 8;
        const uint32_t dst = smb + tz * (128 * AP) + row * AP + u * 16;
        CP_ASYNC16(dst, src);
    }
    a_load_kv(smb, 0, 0, bkv, khi, klo, vhi, vlo);
    CP_COMMIT();

    float m0 = -1e30f, m1 = -1e30f, l0 = 0.f, l1 = 0.f;
    float o[16][4];
#pragma unroll
    for (int i = 0; i < 16; i++)
#pragma unroll
        for (int j = 0; j < 4; j++) o[i][j] = 0.f;

    const int lrow8 = (lane & 7) + ((lane >> 3) & 1) * 8;
    const int lk16  = ((lane >> 4) & 1) * 16;
    const int brow  = (lane & 7);
    const int bk16  = ((lane >> 3) & 1) * 16;
    const int bnf   = ((lane >> 4) & 1) * 8;
    const int rloc  = wid * 16 + (lane >> 2);
    const int rg0   = q0 + rloc;

    for (int kt = 0; kt < nkt; kt++) {
        if (kt + 1 < nkt) {
            a_load_kv(smb, (kt + 1) & 1, kt + 1, bkv, khi, klo, vhi, vlo);
            CP_COMMIT();
            CP_WAIT1();
        } else {
            CP_WAIT0();
        }
        __syncthreads();

        const uint32_t stg = smb + QSMEM + (kt & 1) * KVSTG;
        const uint32_t Khi_s = stg;
        const uint32_t Klo_s = stg + 64 * AP;
        const uint32_t Vhi_s = stg + 128 * AP;
        const uint32_t Vlo_s = stg + 192 * AP;

        float sf[8][4];
#pragma unroll
        for (int i = 0; i < 8; i++)
#pragma unroll
            for (int j = 0; j < 4; j++) sf[i][j] = 0.f;

#pragma unroll
        for (int ks = 0; ks < 8; ks++) {
            const int kb = ks * 32;
            uint32_t ah[4], al[4];
            const uint32_t qoff = (wid * 16 + lrow8) * AP + kb + lk16;
            ldm_x4(ah, smb + qoff);
            ldm_x4(al, smb + 128 * AP + qoff);
#pragma unroll
            for (int nfp = 0; nfp < 4; nfp++) {
                uint32_t bh[4], bl[4];
                const uint32_t boff = (nfp * 16 + bnf + brow) * AP + kb + bk16;
                ldm_x4(bh, Khi_s + boff);
                ldm_x4(bl, Klo_s + boff);
                mma_bf16(sf[nfp * 2 + 0], ah, bh + 0);
                mma_bf16(sf[nfp * 2 + 0], ah, bl + 0);
                mma_bf16(sf[nfp * 2 + 0], al, bh + 0);
                mma_bf16(sf[nfp * 2 + 1], ah, bh + 2);
                mma_bf16(sf[nfp * 2 + 1], ah, bl + 2);
                mma_bf16(sf[nfp * 2 + 1], al, bh + 2);
            }
        }

        const int k0 = kt * 64;
        if (k0 + 63 > rg0) {
#pragma unroll
            for (int nf = 0; nf < 8; nf++) {
                const int cb = k0 + nf * 8 + (lane & 3) * 2;
                if (cb + 0 > rg0)     sf[nf][0] = -1e30f;
                if (cb + 1 > rg0)     sf[nf][1] = -1e30f;
                if (cb + 0 > rg0 + 8) sf[nf][2] = -1e30f;
                if (cb + 1 > rg0 + 8) sf[nf][3] = -1e30f;
            }
        }

        float mx0 = -1e30f, mx1 = -1e30f;
#pragma unroll
        for (int nf = 0; nf < 8; nf++) {
            mx0 = fmaxf(mx0, fmaxf(sf[nf][0], sf[nf][1]));
            mx1 = fmaxf(mx1, fmaxf(sf[nf][2], sf[nf][3]));
        }
        mx0 = fmaxf(mx0, __shfl_xor_sync(0xffffffffu, mx0, 1));
        mx0 = fmaxf(mx0, __shfl_xor_sync(0xffffffffu, mx0, 2));
        mx1 = fmaxf(mx1, __shfl_xor_sync(0xffffffffu, mx1, 1));
        mx1 = fmaxf(mx1, __shfl_xor_sync(0xffffffffu, mx1, 2));

        const float mn0 = fmaxf(m0, mx0);
        const float mn1 = fmaxf(m1, mx1);
        const float a0 = __expf(m0 - mn0);
        const float a1 = __expf(m1 - mn1);
        m0 = mn0; m1 = mn1;

        float rs0 = 0.f, rs1 = 0.f;
#pragma unroll
        for (int nf = 0; nf < 8; nf++) {
            sf[nf][0] = __expf(sf[nf][0] - mn0); rs0 += sf[nf][0];
            sf[nf][1] = __expf(sf[nf][1] - mn0); rs0 += sf[nf][1];
            sf[nf][2] = __expf(sf[nf][2] - mn1); rs1 += sf[nf][2];
            sf[nf][3] = __expf(sf[nf][3] - mn1); rs1 += sf[nf][3];
        }
        rs0 += __shfl_xor_sync(0xffffffffu, rs0, 1);
        rs0 += __shfl_xor_sync(0xffffffffu, rs0, 2);
        rs1 += __shfl_xor_sync(0xffffffffu, rs1, 1);
        rs1 += __shfl_xor_sync(0xffffffffu, rs1, 2);
        l0 = l0 * a0 + rs0;
        l1 = l1 * a1 + rs1;

#pragma unroll
        for (int i = 0; i < 16; i++) {
            o[i][0] *= a0; o[i][1] *= a0; o[i][2] *= a1; o[i][3] *= a1;
        }

#pragma unroll
        for (int kk = 0; kk < 4; kk++) {
            uint32_t ph[4], pl[4];
            float hfr[8], lfr[8];
#pragma unroll
            for (int e = 0; e < 4; e++) {
                float f0 = sf[2 * kk][e];
                float f1 = sf[2 * kk + 1][e];
                float h0 = __bfloat162float(__float2bfloat16(f0));
                float h1 = __bfloat162float(__float2bfloat16(f1));
                hfr[e] = h0; hfr[4 + e] = h1;
                lfr[e] = f0 - h0; lfr[4 + e] = f1 - h1;
            }
            ph[0] = packbf(hfr[0], hfr[1]); ph[1] = packbf(hfr[2], hfr[3]);
            ph[2] = packbf(hfr[4], hfr[5]); ph[3] = packbf(hfr[6], hfr[7]);
            pl[0] = packbf(lfr[0], lfr[1]); pl[1] = packbf(lfr[2], lfr[3]);
            pl[2] = packbf(lfr[4], lfr[5]); pl[3] = packbf(lfr[6], lfr[7]);

#pragma unroll
            for (int db = 0; db < 8; db++) {
                uint32_t vh[4], vl[4];
                const uint32_t voff = (kk * 16 + (lane & 15)) * AP
                                    + (db * 16 + ((lane >> 4) & 1) * 8) * 2;
                ldm_x4_t(vh, Vhi_s + voff);
                ldm_x4_t(vl, Vlo_s + voff);
                mma_bf16(o[db * 2 + 0], ph, vh + 0);
                mma_bf16(o[db * 2 + 0], pl, vh + 0);
                mma_bf16(o[db * 2 + 0], ph, vl + 0);
                mma_bf16(o[db * 2 + 1], ph, vh + 2);
                mma_bf16(o[db * 2 + 1], pl, vh + 2);
                mma_bf16(o[db * 2 + 1], ph, vl + 2);
            }
        }
        __syncthreads();
    }

    const float rv0 = 1.0f / l0;
    const float rv1 = 1.0f / l1;
    const size_t t0 = (size_t)(b * SEQ + rg0);
    const size_t t1 = t0 + 8;
#pragma unroll
    for (int nf = 0; nf < 16; nf++) {
        const int col = h * HD + nf * 8 + (lane & 3) * 2;
        float f0 = o[nf][0] * rv0, f1 = o[nf][1] * rv0;
        float f2 = o[nf][2] * rv1, f3 = o[nf][3] * rv1;
        __nv_bfloat16 h0 = __float2bfloat16(f0), h1 = __float2bfloat16(f1);
        __nv_bfloat16 h2 = __float2bfloat16(f2), h3 = __float2bfloat16(f3);
        *reinterpret_cast<__nv_bfloat162*>(chi + t0 * (NH * HD) + col) = __nv_bfloat162(h0, h1);
        *reinterpret_cast<__nv_bfloat162*>(chi + t1 * (NH * HD) + col) = __nv_bfloat162(h2, h3);
        *reinterpret_cast<__nv_bfloat162*>(clo + t0 * (NH * HD) + col) =
            __nv_bfloat162(__float2bfloat16(f0 - __bfloat162float(h0)),
                           __float2bfloat16(f1 - __bfloat162float(h1)));
        *reinterpret_cast<__nv_bfloat162*>(clo + t1 * (NH * HD) + col) =
            __nv_bfloat162(__float2bfloat16(f2 - __bfloat162float(h2)),
                           __float2bfloat16(f3 - __bfloat162float(h3)));
    }
}

// ============================================================
// launch
// ============================================================
extern "C" void kernel_launch(void* const* d_in, const int* in_sizes, int n_in,
                              void* d_out, int out_size)
{
    const int*   positions = (const int*)  d_in[0];
    const float* hidden    = (const float*)d_in[1];
    const float* kv_in     = (const float*)d_in[2];
    const int*   slot_map  = (const int*)  d_in[4];
    const float* w_qkv     = (const float*)d_in[n_in - 3];
    const float* b_qkv     = (const float*)d_in[n_in - 2];
    const float* w_o       = (const float*)d_in[n_in - 1];

    float* out = (float*)d_out;
    float* kc  = out + (size_t)TTOK * H_DIM;
    float* vc  = kc + CACHE_HALF;

    float *qkv_buf;
    __nv_bfloat16 *h_hi, *h_lo, *wq_hi, *wq_lo, *wo_hi, *wo_lo, *c_hi, *c_lo;
    __nv_bfloat16 *q_hi, *q_lo, *k_hi, *k_lo, *v_hi, *v_lo;
    cudaGetSymbolAddress((void**)&qkv_buf, g_qkv);
    cudaGetSymbolAddress((void**)&h_hi, g_h_hi);
    cudaGetSymbolAddress((void**)&h_lo, g_h_lo);
    cudaGetSymbolAddress((void**)&wq_hi, g_wq_hi);
    cudaGetSymbolAddress((void**)&wq_lo, g_wq_lo);
    cudaGetSymbolAddress((void**)&wo_hi, g_wo_hi);
    cudaGetSymbolAddress((void**)&wo_lo, g_wo_lo);
    cudaGetSymbolAddress((void**)&c_hi, g_c_hi);
    cudaGetSymbolAddress((void**)&c_lo, g_c_lo);
    cudaGetSymbolAddress((void**)&q_hi, g_q_hi);
    cudaGetSymbolAddress((void**)&q_lo, g_q_lo);
    cudaGetSymbolAddress((void**)&k_hi, g_k_hi);
    cudaGetSymbolAddress((void**)&k_lo, g_k_lo);
    cudaGetSymbolAddress((void**)&v_hi, g_v_hi);
    cudaGetSymbolAddress((void**)&v_lo, g_v_lo);

    cudaMemcpyAsync(kc, kv_in, (size_t)2 * CACHE_HALF * sizeof(float),
                    cudaMemcpyDeviceToDevice, 0);

    split_bf16<<<2048, 256>>>(hidden, h_hi, h_lo, TTOK * KDIM / 4);
    split_bf16<<<2048, 256>>>(w_qkv, wq_hi, wq_lo, QKV_OUT * KDIM / 4);
    split_bf16<<<2048, 256>>>(w_o, wo_hi, wo_lo, H_DIM * KDIM / 4);

    cudaFuncSetAttribute(gemm_tc, cudaFuncAttributeMaxDynamicSharedMemorySize, GEMM_SMEM);

    // 1) qkv = hidden @ w_qkv^T + b
    gemm_tc<<<dim3(QKV_OUT/128, TTOK/128), 256, GEMM_SMEM>>>(
        h_hi, h_lo, wq_hi, wq_lo, b_qkv, qkv_buf, QKV_OUT);

    // 2) rope + scatter + bf16 emission
    rope_scatter<<<TTOK, 256>>>(qkv_buf, positions, slot_map, kc, vc,
                                q_hi, q_lo, k_hi, k_lo, v_hi, v_lo);

    // 3) tensor-core attention (writes ctx hi/lo directly)
    cudaFuncSetAttribute(attn_tc, cudaFuncAttributeMaxDynamicSharedMemorySize, ATTN_SMEM);
    attn_tc<<<dim3(SEQ/128, NH, BATCH), 256, ATTN_SMEM>>>(
        q_hi, q_lo, k_hi, k_lo, v_hi, v_lo, c_hi, c_lo);

    // 4) out = ctx @ w_o^T
    gemm_tc<<<dim3(H_DIM/128, TTOK/128), 256, GEMM_SMEM>>>(
        c_hi, c_lo, wo_hi, wo_lo, nullptr, out, H_DIM);
}